// round 16
// baseline (speedup 1.0000x reference)
#include <cuda_runtime.h>
#include <cuda_bf16.h>
#include <mma.h>
#include <math.h>
#include <stdint.h>

using namespace nvcuda;

// Problem dims (fixed by setup_inputs)
#define NN 2048   // nodes
#define BB 32     // batch
#define DD 64     // hidden dim
#define D2 128    // 2*hidden
#define EE 10     // embed dim
#define KK 3      // cheb order
#define PG (KK*DD*D2)   // 24576
#define PU (KK*D2*DD)   // 24576

#define NCOLS 2048      // all GEMMs: Ncols = BB*DD (x-half eliminated by algebra)

// WMMA GEMM tiling: 128x128 CTA tile, 256 threads, 3-stage cp.async, 2 CTAs/SM
#define CTM 128
#define CTN 128
#define CTK 32
#define STAGES 3
#define A_LD 40
#define B_LD 136
#define A_TILE_B (CTM*A_LD*2)        // 10240
#define B_TILE_B (CTK*B_LD*2)        // 8704
#define STAGE_B  (2*A_TILE_B + 2*B_TILE_B)  // 37888
#define HG_SMEM  (STAGES*STAGE_B)    // 113664

// Mix kernels (wmma): smem budgets
#define GATE_SMEM (192*D2*2*2 + BB*192*2*2)   // Wh+Wl (96KB) + Avh+Avl (24KB) = 122880
#define UPD_SMEM  (384*DD*2*2 + BB*384*2*2)   // 96KB + 48KB = 147456

// -------- device scratch (static allocation — no runtime allocs) --------
__device__ float g_Xt  [NN*BB*DD];
__device__ float g_G1  [NN*BB*DD];
__device__ float g_G2  [NN*BB*DD];
__device__ float g_R   [NN*BB*DD];
__device__ float g_Cz  [NN*BB*DD];
__device__ float g_H1z [NN*BB*DD];
__device__ float g_H2z [NN*BB*DD];
__device__ float g_Bg  [NN*D2];
__device__ float g_Bu  [NN*DD];

// bf16 hi/lo split operands
__device__ __align__(16) __nv_bfloat16 bAh  [NN*NN];
__device__ __align__(16) __nv_bfloat16 bAl  [NN*NN];
__device__ __align__(16) __nv_bfloat16 bXh  [NN*BB*DD];
__device__ __align__(16) __nv_bfloat16 bXl  [NN*BB*DD];
__device__ __align__(16) __nv_bfloat16 bG1h [NN*BB*DD];
__device__ __align__(16) __nv_bfloat16 bG1l [NN*BB*DD];
__device__ __align__(16) __nv_bfloat16 bG2h [NN*BB*DD];
__device__ __align__(16) __nv_bfloat16 bG2l [NN*BB*DD];
__device__ __align__(16) __nv_bfloat16 bCzh [NN*BB*DD];
__device__ __align__(16) __nv_bfloat16 bCzl [NN*BB*DD];
__device__ __align__(16) __nv_bfloat16 bH1zh[NN*BB*DD];
__device__ __align__(16) __nv_bfloat16 bH1zl[NN*BB*DD];
__device__ __align__(16) __nv_bfloat16 bH2zh[NN*BB*DD];
__device__ __align__(16) __nv_bfloat16 bH2zl[NN*BB*DD];

// per-node weights, bf16 hi/lo (replaces fp32 g_Wg/g_Wu; same total bytes)
__device__ __align__(16) __nv_bfloat16 bWgh[(size_t)NN*PG];
__device__ __align__(16) __nv_bfloat16 bWgl[(size_t)NN*PG];
__device__ __align__(16) __nv_bfloat16 bWuh[(size_t)NN*PU];
__device__ __align__(16) __nv_bfloat16 bWul[(size_t)NN*PU];

// =====================================================================
// helpers
// =====================================================================
__device__ __forceinline__ uint32_t smem_u32(const void* p) {
    uint32_t a;
    asm("{ .reg .u64 t; cvta.to.shared.u64 t, %1; cvt.u32.u64 %0, t; }" : "=r"(a) : "l"(p));
    return a;
}
#define CP16(dst, src) asm volatile("cp.async.cg.shared.global [%0], [%1], 16;" :: "r"(dst), "l"(src))
#define CP_COMMIT()    asm volatile("cp.async.commit_group;")
#define CP_WAIT1()     asm volatile("cp.async.wait_group 1;")
#define CP_WAIT0()     asm volatile("cp.async.wait_group 0;")

__device__ __forceinline__ void split2(float a, float b, uint32_t& hi, uint32_t& lo) {
    __nv_bfloat16 ah = __float2bfloat16(a), bh = __float2bfloat16(b);
    float ar = a - __bfloat162float(ah), br = b - __bfloat162float(bh);
    __nv_bfloat16 al = __float2bfloat16(ar), bl = __float2bfloat16(br);
    hi = (uint32_t)__bfloat16_as_ushort(ah) | ((uint32_t)__bfloat16_as_ushort(bh) << 16);
    lo = (uint32_t)__bfloat16_as_ushort(al) | ((uint32_t)__bfloat16_as_ushort(bl) << 16);
}

// =====================================================================
// adj = softmax(relu(emb @ emb^T), axis=1) -> bf16 hi/lo directly
// =====================================================================
__global__ __launch_bounds__(256) void adj_kernel(const float* __restrict__ emb) {
    __shared__ float row[NN];
    __shared__ float red[256];
    const int n = blockIdx.x;
    const int tid = threadIdx.x;
    float en[EE];
#pragma unroll
    for (int e = 0; e < EE; e++) en[e] = emb[n*EE + e];
    float lmax = 0.f;
    for (int m = tid; m < NN; m += 256) {
        float s = 0.f;
#pragma unroll
        for (int e = 0; e < EE; e++) s = fmaf(en[e], emb[m*EE + e], s);
        s = fmaxf(s, 0.f);
        row[m] = s;
        lmax = fmaxf(lmax, s);
    }
    red[tid] = lmax; __syncthreads();
    for (int s = 128; s > 0; s >>= 1) { if (tid < s) red[tid] = fmaxf(red[tid], red[tid+s]); __syncthreads(); }
    const float gmax = red[0];
    __syncthreads();
    float lsum = 0.f;
    for (int m = tid; m < NN; m += 256) { float v = __expf(row[m] - gmax); row[m] = v; lsum += v; }
    red[tid] = lsum; __syncthreads();
    for (int s = 128; s > 0; s >>= 1) { if (tid < s) red[tid] += red[tid+s]; __syncthreads(); }
    const float inv = 1.f / red[0];
    __syncthreads();
    const int m0 = tid * 8;
    uint32_t hp[4], lp[4];
#pragma unroll
    for (int p = 0; p < 4; p++)
        split2(row[m0 + 2*p] * inv, row[m0 + 2*p + 1] * inv, hp[p], lp[p]);
    *(uint4*)&bAh[(size_t)n*NN + m0] = make_uint4(hp[0], hp[1], hp[2], hp[3]);
    *(uint4*)&bAl[(size_t)n*NN + m0] = make_uint4(lp[0], lp[1], lp[2], lp[3]);
}

// =====================================================================
// Transpose x (B,N,D) -> Xt (N,B,D) fp32 + fused bf16 hi/lo split
// =====================================================================
__global__ __launch_bounds__(256) void transpose_kernel(const float* __restrict__ x) {
    int idx = blockIdx.x * 256 + threadIdx.x;
    int d4 = idx & 15;
    int b  = (idx >> 4) & 31;
    int n  = idx >> 9;
    float4 v = *(const float4*)&x[((size_t)b*NN + n)*DD + d4*4];
    size_t off = ((size_t)n*BB + b)*DD + d4*4;
    *(float4*)&g_Xt[off] = v;
    uint2 hi, lo;
    split2(v.x, v.y, hi.x, lo.x);
    split2(v.z, v.w, hi.y, lo.y);
    *(uint2*)&bXh[off] = hi;
    *(uint2*)&bXl[off] = lo;
}

// =====================================================================
// Per-node weight materialization -> bf16 hi/lo directly.
// Output symbols resolved in DEVICE code (host shadow-symbol ATS hazard).
// =====================================================================
__global__ __launch_bounds__(256) void wgen_kernel(int which,
                                                   const float* __restrict__ emb,
                                                   const float* __restrict__ pool) {
    __nv_bfloat16* outH = (which == 0) ? bWgh : bWuh;
    __nv_bfloat16* outL = (which == 0) ? bWgl : bWul;
    __shared__ float es[128*EE];
    const int j4 = blockIdx.x * 256 + threadIdx.x;   // float4 index in [0, PG/4)
    const int nbase = blockIdx.y * 128;
    for (int i = threadIdx.x; i < 128*EE; i += 256)
        es[i] = emb[nbase*EE + i];
    float4 pv[EE];
#pragma unroll
    for (int e = 0; e < EE; e++) pv[e] = ((const float4*)(pool + (size_t)e*PG))[j4];
    __syncthreads();
    for (int n = 0; n < 128; n++) {
        const float* er = es + n*EE;
        float4 a = make_float4(0.f, 0.f, 0.f, 0.f);
#pragma unroll
        for (int e = 0; e < EE; e++) {
            float w = er[e];
            a.x = fmaf(w, pv[e].x, a.x); a.y = fmaf(w, pv[e].y, a.y);
            a.z = fmaf(w, pv[e].z, a.z); a.w = fmaf(w, pv[e].w, a.w);
        }
        uint2 hi, lo;
        split2(a.x, a.y, hi.x, lo.x);
        split2(a.z, a.w, hi.y, lo.y);
        ((uint2*)(outH + (size_t)(nbase + n)*PG))[j4] = hi;
        ((uint2*)(outL + (size_t)(nbase + n)*PG))[j4] = lo;
    }
}

__device__ __forceinline__ void bgen_body(const float* __restrict__ emb,
                                          const float* __restrict__ bpool,
                                          float* __restrict__ out, int P) {
    int idx = blockIdx.x * 256 + threadIdx.x;
    if (idx >= NN * P) return;
    int n = idx / P, p = idx - n * P;
    float acc = 0.f;
#pragma unroll
    for (int e = 0; e < EE; e++) acc = fmaf(emb[n*EE + e], bpool[e*P + p], acc);
    out[idx] = acc;
}
__global__ __launch_bounds__(256) void bgen_gate(const float* emb, const float* bp) { bgen_body(emb, bp, g_Bg, D2); }
__global__ __launch_bounds__(256) void bgen_upd (const float* emb, const float* bp) { bgen_body(emb, bp, g_Bu, DD); }

// =====================================================================
// WMMA bf16-split GEMM: Out = alpha*(A@B) + beta*Cs  [+ fused bf16 split]
// =====================================================================
__global__ __launch_bounds__(256, 2) void hgemm_kernel(int which) {
    const __nv_bfloat16 *gBh, *gBl;
    float* Out; const float* Cs; float alpha, beta;
    __nv_bfloat16 *Oh, *Ol;
    switch (which) {
        case 0:  gBh = bXh;   gBl = bXl;   Out = g_G1;  Cs = nullptr; alpha = 1.f; beta =  0.f; Oh = bG1h;  Ol = bG1l;  break;
        case 1:  gBh = bG1h;  gBl = bG1l;  Out = g_G2;  Cs = g_Xt;    alpha = 2.f; beta = -1.f; Oh = bG2h;  Ol = bG2l;  break;
        case 2:  gBh = bCzh;  gBl = bCzl;  Out = g_H1z; Cs = nullptr; alpha = 1.f; beta =  0.f; Oh = bH1zh; Ol = bH1zl; break;
        default: gBh = bH1zh; gBl = bH1zl; Out = g_H2z; Cs = g_Cz;    alpha = 2.f; beta = -1.f; Oh = bH2zh; Ol = bH2zl; break;
    }
    extern __shared__ __align__(16) char smem[];
    const uint32_t sb = smem_u32(smem);
    const int tid  = threadIdx.x;
    const int lane = tid & 31;
    const int wid  = tid >> 5;
    const int wm   = (wid & 3) * 32;
    const int wn   = (wid >> 2) * 64;
    const int mBase = blockIdx.y * CTM;
    const int nBase = blockIdx.x * CTN;

    const int aRow = tid >> 2,  aC = tid & 3;
    const int bRow = tid >> 4,  bC = tid & 15;
    auto load_stage = [&](int it, int s) {
        const int k0 = it * CTK;
        const uint32_t st = sb + s * STAGE_B;
#pragma unroll
        for (int i = 0; i < 2; i++) {
            int row = aRow + i*64;
            uint32_t d = st + row*(A_LD*2) + aC*16;
            size_t g = (size_t)(mBase + row)*NN + k0 + aC*8;
            CP16(d,            bAh + g);
            CP16(d + A_TILE_B, bAl + g);
        }
#pragma unroll
        for (int i = 0; i < 2; i++) {
            int row = bRow + i*16;
            uint32_t d = st + 2*A_TILE_B + row*(B_LD*2) + bC*16;
            size_t g = (size_t)(k0 + row)*NCOLS + nBase + bC*8;
            CP16(d,            gBh + g);
            CP16(d + B_TILE_B, gBl + g);
        }
        CP_COMMIT();
    };

    wmma::fragment<wmma::accumulator, 16, 16, 16, float> acc[2][4];
#pragma unroll
    for (int mi = 0; mi < 2; mi++)
#pragma unroll
        for (int ni = 0; ni < 4; ni++)
            wmma::fill_fragment(acc[mi][ni], 0.f);

    load_stage(0, 0);
    load_stage(1, 1);

    const int k_iters = NN / CTK;   // 64
    for (int it = 0; it < k_iters; it++) {
        const int s = it % STAGES;
        if (it + 1 < k_iters) { CP_WAIT1(); } else { CP_WAIT0(); }
        __syncthreads();
        if (it + 2 < k_iters) load_stage(it + 2, (it + 2) % STAGES);

        const __nv_bfloat16* Ah = (const __nv_bfloat16*)(smem + s*STAGE_B);
        const __nv_bfloat16* Al = Ah + CTM*A_LD;
        const __nv_bfloat16* Bh = (const __nv_bfloat16*)(smem + s*STAGE_B + 2*A_TILE_B);
        const __nv_bfloat16* Bl = Bh + CTK*B_LD;

#pragma unroll
        for (int kk = 0; kk < CTK; kk += 16) {
            wmma::fragment<wmma::matrix_a, 16, 16, 16, __nv_bfloat16, wmma::row_major> ah[2], al[2];
#pragma unroll
            for (int mi = 0; mi < 2; mi++) {
                wmma::load_matrix_sync(ah[mi], Ah + (wm + mi*16)*A_LD + kk, A_LD);
                wmma::load_matrix_sync(al[mi], Al + (wm + mi*16)*A_LD + kk, A_LD);
            }
#pragma unroll
            for (int ni = 0; ni < 4; ni++) {
                wmma::fragment<wmma::matrix_b, 16, 16, 16, __nv_bfloat16, wmma::row_major> bh, bl;
                wmma::load_matrix_sync(bh, Bh + kk*B_LD + wn + ni*16, B_LD);
                wmma::load_matrix_sync(bl, Bl + kk*B_LD + wn + ni*16, B_LD);
#pragma unroll
                for (int mi = 0; mi < 2; mi++) {
                    wmma::mma_sync(acc[mi][ni], ah[mi], bh, acc[mi][ni]);
                    wmma::mma_sync(acc[mi][ni], al[mi], bh, acc[mi][ni]);
                    wmma::mma_sync(acc[mi][ni], ah[mi], bl, acc[mi][ni]);
                }
            }
        }
        __syncthreads();
    }

    __syncthreads();
    float* stage = (float*)smem + wid * (32*64);
#pragma unroll
    for (int mi = 0; mi < 2; mi++)
#pragma unroll
        for (int ni = 0; ni < 4; ni++) {
            if (alpha != 1.f) {
#pragma unroll
                for (int e = 0; e < acc[mi][ni].num_elements; e++)
                    acc[mi][ni].x[e] *= alpha;
            }
            wmma::store_matrix_sync(stage + mi*16*64 + ni*16, acc[mi][ni], 64, wmma::mem_row_major);
        }
    __syncwarp();

    const int col = nBase + wn + lane*2;
    for (int r = 0; r < 32; r++) {
        const int row = mBase + wm + r;
        float2 v = *(const float2*)&stage[r*64 + lane*2];
        const size_t off = (size_t)row*NCOLS + col;
        if (Cs) {
            float2 cv = *(const float2*)&Cs[off];
            v.x = fmaf(beta, cv.x, v.x);
            v.y = fmaf(beta, cv.y, v.y);
        }
        *(float2*)&Out[off] = v;
        if (Oh) {
            uint32_t hi, lo;
            split2(v.x, v.y, hi, lo);
            *(uint32_t*)&Oh[off] = hi;
            *(uint32_t*)&Ol[off] = lo;
        }
    }
}

// =====================================================================
// Gate mix (wmma): zr = Av(32x192) @ Wg(192x128) + Bg; sigmoid
// Av = [x|G1|G2] bf16 hi/lo; W = bWgh/bWgl. 3-term split, fp32 accum.
// z -> g_Cz (+ bf16 split), r -> g_R
// =====================================================================
__global__ __launch_bounds__(256) void gate_mix_kernel() {
    extern __shared__ __align__(16) char sm[];
    __nv_bfloat16* Wh  = (__nv_bfloat16*)sm;        // 192x128
    __nv_bfloat16* Wl  = Wh + 192*D2;
    __nv_bfloat16* Avh = Wl + 192*D2;               // 32x192
    __nv_bfloat16* Avl = Avh + BB*192;
    float* stage = (float*)(Wl + 192*D2);           // reuse Av region post-sync

    const int n = blockIdx.x;
    const int tid = threadIdx.x;
    const int wid = tid >> 5;

    // stage W (hi/lo): PG bf16 each = 3072 uint4
    {
        const uint4* srcH = (const uint4*)(bWgh + (size_t)n*PG);
        const uint4* srcL = (const uint4*)(bWgl + (size_t)n*PG);
        uint4* dH = (uint4*)Wh; uint4* dL = (uint4*)Wl;
        for (int i = tid; i < PG/8; i += 256) { dH[i] = srcH[i]; dL[i] = srcL[i]; }
    }
    // stage Av: row b, cols [x(0:64)|G1(64:128)|G2(128:192)]
    {
        const size_t base = (size_t)n*BB*DD;
        const uint32_t* sH; const uint32_t* sL;
#pragma unroll
        for (int k = 0; k < 3; k++) {
            if (k == 0)      { sH = (const uint32_t*)(bXh  + base); sL = (const uint32_t*)(bXl  + base); }
            else if (k == 1) { sH = (const uint32_t*)(bG1h + base); sL = (const uint32_t*)(bG1l + base); }
            else             { sH = (const uint32_t*)(bG2h + base); sL = (const uint32_t*)(bG2l + base); }
            for (int t = tid; t < BB*32; t += 256) {   // 32 uint32 per row
                int b = t >> 5, i2 = t & 31;
                ((uint32_t*)(Avh + b*192 + k*64))[i2] = sH[b*32 + i2];
                ((uint32_t*)(Avl + b*192 + k*64))[i2] = sL[b*32 + i2];
            }
        }
    }
    __syncthreads();

    // warp wid handles o-tile [wid*16, +16), m-tiles 0..1
    wmma::fragment<wmma::accumulator, 16, 16, 16, float> acc[2];
    wmma::fill_fragment(acc[0], 0.f);
    wmma::fill_fragment(acc[1], 0.f);
#pragma unroll
    for (int kt = 0; kt < 12; kt++) {
        wmma::fragment<wmma::matrix_a, 16, 16, 16, __nv_bfloat16, wmma::row_major> ah[2], al[2];
#pragma unroll
        for (int mi = 0; mi < 2; mi++) {
            wmma::load_matrix_sync(ah[mi], Avh + (mi*16)*192 + kt*16, 192);
            wmma::load_matrix_sync(al[mi], Avl + (mi*16)*192 + kt*16, 192);
        }
        wmma::fragment<wmma::matrix_b, 16, 16, 16, __nv_bfloat16, wmma::row_major> bh, bl;
        wmma::load_matrix_sync(bh, Wh + (kt*16)*D2 + wid*16, D2);
        wmma::load_matrix_sync(bl, Wl + (kt*16)*D2 + wid*16, D2);
#pragma unroll
        for (int mi = 0; mi < 2; mi++) {
            wmma::mma_sync(acc[mi], ah[mi], bh, acc[mi]);
            wmma::mma_sync(acc[mi], al[mi], bh, acc[mi]);
            wmma::mma_sync(acc[mi], ah[mi], bl, acc[mi]);
        }
    }
    __syncthreads();   // Av region now dead -> stage
#pragma unroll
    for (int mi = 0; mi < 2; mi++)
        wmma::store_matrix_sync(stage + mi*16*D2 + wid*16, acc[mi], D2, wmma::mem_row_major);
    __syncthreads();

    // epilogue: 32x128 outputs as quads
    for (int q = tid; q < BB*D2/4; q += 256) {
        int b = q >> 5, o = (q & 31) * 4;
        float4 v = *(const float4*)&stage[b*D2 + o];
        float4 sv;
        sv.x = 1.f / (1.f + __expf(-(v.x + g_Bg[n*D2 + o + 0])));
        sv.y = 1.f / (1.f + __expf(-(v.y + g_Bg[n*D2 + o + 1])));
        sv.z = 1.f / (1.f + __expf(-(v.z + g_Bg[n*D2 + o + 2])));
        sv.w = 1.f / (1.f + __expf(-(v.w + g_Bg[n*D2 + o + 3])));
        if (o < DD) {
            size_t off = ((size_t)n*BB + b)*DD + o;
            *(float4*)&g_Cz[off] = sv;
            uint2 hi, lo;
            split2(sv.x, sv.y, hi.x, lo.x);
            split2(sv.z, sv.w, hi.y, lo.y);
            *(uint2*)&bCzh[off] = hi;
            *(uint2*)&bCzl[off] = lo;
        } else {
            *(float4*)&g_R[((size_t)n*BB + b)*DD + (o - DD)] = sv;
        }
    }
}

// =====================================================================
// Update mix (wmma): hc = tanh(Av(32x384) @ Wu(384x64) + Bu)
// Av = [x|z|G1|H1z|G2|H2z] bf16 hi/lo. h = r*x + (1-r)*hc -> out (B,N,D)
// =====================================================================
__global__ __launch_bounds__(256) void update_mix_kernel(float* __restrict__ out) {
    extern __shared__ __align__(16) char sm[];
    __nv_bfloat16* Wh  = (__nv_bfloat16*)sm;        // 384x64
    __nv_bfloat16* Wl  = Wh + 384*DD;
    __nv_bfloat16* Avh = Wl + 384*DD;               // 32x384
    __nv_bfloat16* Avl = Avh + BB*384;
    float* stage = (float*)(Wl + 384*DD);           // reuse Av region post-sync

    const int n = blockIdx.x;
    const int tid = threadIdx.x;
    const int wid = tid >> 5;

    {
        const uint4* srcH = (const uint4*)(bWuh + (size_t)n*PU);
        const uint4* srcL = (const uint4*)(bWul + (size_t)n*PU);
        uint4* dH = (uint4*)Wh; uint4* dL = (uint4*)Wl;
        for (int i = tid; i < PU/8; i += 256) { dH[i] = srcH[i]; dL[i] = srcL[i]; }
    }
    {
        const size_t base = (size_t)n*BB*DD;
        const uint32_t* sH; const uint32_t* sL;
#pragma unroll
        for (int k = 0; k < 6; k++) {
            switch (k) {
                case 0: sH = (const uint32_t*)(bXh   + base); sL = (const uint32_t*)(bXl   + base); break;
                case 1: sH = (const uint32_t*)(bCzh  + base); sL = (const uint32_t*)(bCzl  + base); break;
                case 2: sH = (const uint32_t*)(bG1h  + base); sL = (const uint32_t*)(bG1l  + base); break;
                case 3: sH = (const uint32_t*)(bH1zh + base); sL = (const uint32_t*)(bH1zl + base); break;
                case 4: sH = (const uint32_t*)(bG2h  + base); sL = (const uint32_t*)(bG2l  + base); break;
                default:sH = (const uint32_t*)(bH2zh + base); sL = (const uint32_t*)(bH2zl + base); break;
            }
            for (int t = tid; t < BB*32; t += 256) {
                int b = t >> 5, i2 = t & 31;
                ((uint32_t*)(Avh + b*384 + k*64))[i2] = sH[b*32 + i2];
                ((uint32_t*)(Avl + b*384 + k*64))[i2] = sL[b*32 + i2];
            }
        }
    }
    __syncthreads();

    // warp wid: mi = wid & 1, ni = wid >> 1 (4 o-tiles of 16)
    const int mi = wid & 1;
    const int ni = wid >> 1;
    wmma::fragment<wmma::accumulator, 16, 16, 16, float> acc;
    wmma::fill_fragment(acc, 0.f);
#pragma unroll
    for (int kt = 0; kt < 24; kt++) {
        wmma::fragment<wmma::matrix_a, 16, 16, 16, __nv_bfloat16, wmma::row_major> ah, al;
        wmma::load_matrix_sync(ah, Avh + (mi*16)*384 + kt*16, 384);
        wmma::load_matrix_sync(al, Avl + (mi*16)*384 + kt*16, 384);
        wmma::fragment<wmma::matrix_b, 16, 16, 16, __nv_bfloat16, wmma::row_major> bh, bl;
        wmma::load_matrix_sync(bh, Wh + (kt*16)*DD + ni*16, DD);
        wmma::load_matrix_sync(bl, Wl + (kt*16)*DD + ni*16, DD);
        wmma::mma_sync(acc, ah, bh, acc);
        wmma::mma_sync(acc, al, bh, acc);
        wmma::mma_sync(acc, ah, bl, acc);
    }
    __syncthreads();
    wmma::store_matrix_sync(stage + (mi*16)*DD + ni*16, acc, DD, wmma::mem_row_major);
    __syncthreads();

    // epilogue: 32x64 outputs as quads (512 quads / 256 threads = 2 each)
    for (int q = tid; q < BB*DD/4; q += 256) {
        int b = q >> 4, o = (q & 15) * 4;
        float4 v = *(const float4*)&stage[b*DD + o];
        const size_t rx = ((size_t)n*BB + b)*DD + o;
        float4 rv = *(const float4*)&g_R[rx];
        float4 xv = *(const float4*)&g_Xt[rx];
        float4 ov;
        float hc;
        hc = tanhf(v.x + g_Bu[n*DD + o + 0]); ov.x = fmaf(rv.x, xv.x - hc, hc);
        hc = tanhf(v.y + g_Bu[n*DD + o + 1]); ov.y = fmaf(rv.y, xv.y - hc, hc);
        hc = tanhf(v.z + g_Bu[n*DD + o + 2]); ov.z = fmaf(rv.z, xv.z - hc, hc);
        hc = tanhf(v.w + g_Bu[n*DD + o + 3]); ov.w = fmaf(rv.w, xv.w - hc, hc);
        *(float4*)&out[((size_t)b*NN + n)*DD + o] = ov;
    }
}

// =====================================================================
// Launch
// =====================================================================
extern "C" void kernel_launch(void* const* d_in, const int* in_sizes, int n_in,
                              void* d_out, int out_size) {
    const float* x   = (const float*)d_in[0];
    const float* emb = (const float*)d_in[2];
    const float* gwp = (const float*)d_in[3];
    const float* gbp = (const float*)d_in[4];
    const float* uwp = (const float*)d_in[5];
    const float* ubp = (const float*)d_in[6];
    float* out = (float*)d_out;

    cudaFuncSetAttribute(gate_mix_kernel,   cudaFuncAttributeMaxDynamicSharedMemorySize, GATE_SMEM);
    cudaFuncSetAttribute(update_mix_kernel, cudaFuncAttributeMaxDynamicSharedMemorySize, UPD_SMEM);
    cudaFuncSetAttribute(hgemm_kernel,      cudaFuncAttributeMaxDynamicSharedMemorySize, HG_SMEM);

    const dim3 GEMM_GRID(NCOLS/CTN, NN/CTM);   // (16, 16) = 256 CTAs

    adj_kernel<<<NN, 256>>>(emb);                            // adj -> bAh/bAl
    transpose_kernel<<<(NN*BB*16)/256, 256>>>(x);            // Xt + bXh/bXl
    wgen_kernel<<<dim3(PG/1024, NN/128), 256>>>(0, emb, gwp);// -> bWgh/bWgl
    wgen_kernel<<<dim3(PU/1024, NN/128), 256>>>(1, emb, uwp);// -> bWuh/bWul

    hgemm_kernel<<<GEMM_GRID, 256, HG_SMEM>>>(0);            // G1 = A@x   (+split)
    hgemm_kernel<<<GEMM_GRID, 256, HG_SMEM>>>(1);            // G2 = 2A@G1 - x (+split)

    bgen_gate<<<(NN*D2 + 255)/256, 256>>>(emb, gbp);
    bgen_upd <<<(NN*DD + 255)/256, 256>>>(emb, ubp);

    gate_mix_kernel<<<NN, 256, GATE_SMEM>>>();               // z (+split), r

    hgemm_kernel<<<GEMM_GRID, 256, HG_SMEM>>>(2);            // H1z = A@z (+split)
    hgemm_kernel<<<GEMM_GRID, 256, HG_SMEM>>>(3);            // H2z = 2A@H1z - z (+split)

    update_mix_kernel<<<NN, 256, UPD_SMEM>>>(out);
}

// round 17
// speedup vs baseline: 1.2815x; 1.2815x over previous
#include <cuda_runtime.h>
#include <cuda_bf16.h>
#include <mma.h>
#include <math.h>
#include <stdint.h>

using namespace nvcuda;

// Problem dims (fixed by setup_inputs)
#define NN 2048   // nodes
#define BB 32     // batch
#define DD 64     // hidden dim
#define D2 128    // 2*hidden
#define EE 10     // embed dim
#define KK 3      // cheb order
#define PG (KK*DD*D2)   // 24576
#define PU (KK*D2*DD)   // 24576

#define NCOLS 2048      // all GEMMs: Ncols = BB*DD (x-half eliminated by algebra)

// WMMA GEMM tiling: 128x128 CTA tile, 256 threads, 3-stage cp.async, 2 CTAs/SM
#define CTM 128
#define CTN 128
#define CTK 32
#define STAGES 3
#define A_LD 40
#define B_LD 136
#define A_TILE_B (CTM*A_LD*2)        // 10240
#define B_TILE_B (CTK*B_LD*2)        // 8704
#define STAGE_B  (2*A_TILE_B + 2*B_TILE_B)  // 37888
#define HG_SMEM  (STAGES*STAGE_B)    // 113664

// -------- device scratch (static allocation — no runtime allocs) --------
__device__ float g_Xt  [NN*BB*DD];
__device__ float g_G1  [NN*BB*DD];
__device__ float g_G2  [NN*BB*DD];
__device__ float g_R   [NN*BB*DD];
__device__ float g_Cz  [NN*BB*DD];   // z gate (candidate second half)
__device__ float g_H1z [NN*BB*DD];   // A @ z
__device__ float g_H2z [NN*BB*DD];   // 2A@H1z - z
__device__ float g_Wg  [(size_t)NN*PG];
__device__ float g_Wu  [(size_t)NN*PU];

// bf16 hi/lo split operands (layouts identical to their fp32 sources)
__device__ __align__(16) __nv_bfloat16 bAh  [NN*NN];
__device__ __align__(16) __nv_bfloat16 bAl  [NN*NN];
__device__ __align__(16) __nv_bfloat16 bXh  [NN*BB*DD];
__device__ __align__(16) __nv_bfloat16 bXl  [NN*BB*DD];
__device__ __align__(16) __nv_bfloat16 bG1h [NN*BB*DD];
__device__ __align__(16) __nv_bfloat16 bG1l [NN*BB*DD];
__device__ __align__(16) __nv_bfloat16 bCzh [NN*BB*DD];
__device__ __align__(16) __nv_bfloat16 bCzl [NN*BB*DD];
__device__ __align__(16) __nv_bfloat16 bH1zh[NN*BB*DD];
__device__ __align__(16) __nv_bfloat16 bH1zl[NN*BB*DD];

// =====================================================================
// helpers
// =====================================================================
__device__ __forceinline__ uint32_t smem_u32(const void* p) {
    uint32_t a;
    asm("{ .reg .u64 t; cvta.to.shared.u64 t, %1; cvt.u32.u64 %0, t; }" : "=r"(a) : "l"(p));
    return a;
}
#define CP16(dst, src) asm volatile("cp.async.cg.shared.global [%0], [%1], 16;" :: "r"(dst), "l"(src))
#define CP_COMMIT()    asm volatile("cp.async.commit_group;")
#define CP_WAIT1()     asm volatile("cp.async.wait_group 1;")
#define CP_WAIT0()     asm volatile("cp.async.wait_group 0;")

__device__ __forceinline__ void split2(float a, float b, uint32_t& hi, uint32_t& lo) {
    __nv_bfloat16 ah = __float2bfloat16(a), bh = __float2bfloat16(b);
    float ar = a - __bfloat162float(ah), br = b - __bfloat162float(bh);
    __nv_bfloat16 al = __float2bfloat16(ar), bl = __float2bfloat16(br);
    hi = (uint32_t)__bfloat16_as_ushort(ah) | ((uint32_t)__bfloat16_as_ushort(bh) << 16);
    lo = (uint32_t)__bfloat16_as_ushort(al) | ((uint32_t)__bfloat16_as_ushort(bl) << 16);
}

// =====================================================================
// adj = softmax(relu(emb @ emb^T), axis=1) -> bf16 hi/lo directly
// =====================================================================
__global__ __launch_bounds__(256) void adj_kernel(const float* __restrict__ emb) {
    __shared__ float row[NN];
    __shared__ float red[256];
    const int n = blockIdx.x;
    const int tid = threadIdx.x;
    float en[EE];
#pragma unroll
    for (int e = 0; e < EE; e++) en[e] = emb[n*EE + e];
    float lmax = 0.f;
    for (int m = tid; m < NN; m += 256) {
        float s = 0.f;
#pragma unroll
        for (int e = 0; e < EE; e++) s = fmaf(en[e], emb[m*EE + e], s);
        s = fmaxf(s, 0.f);
        row[m] = s;
        lmax = fmaxf(lmax, s);
    }
    red[tid] = lmax; __syncthreads();
    for (int s = 128; s > 0; s >>= 1) { if (tid < s) red[tid] = fmaxf(red[tid], red[tid+s]); __syncthreads(); }
    const float gmax = red[0];
    __syncthreads();
    float lsum = 0.f;
    for (int m = tid; m < NN; m += 256) { float v = __expf(row[m] - gmax); row[m] = v; lsum += v; }
    red[tid] = lsum; __syncthreads();
    for (int s = 128; s > 0; s >>= 1) { if (tid < s) red[tid] += red[tid+s]; __syncthreads(); }
    const float inv = 1.f / red[0];
    __syncthreads();
    const int m0 = tid * 8;
    uint32_t hp[4], lp[4];
#pragma unroll
    for (int p = 0; p < 4; p++)
        split2(row[m0 + 2*p] * inv, row[m0 + 2*p + 1] * inv, hp[p], lp[p]);
    *(uint4*)&bAh[(size_t)n*NN + m0] = make_uint4(hp[0], hp[1], hp[2], hp[3]);
    *(uint4*)&bAl[(size_t)n*NN + m0] = make_uint4(lp[0], lp[1], lp[2], lp[3]);
}

// =====================================================================
// Transpose x (B,N,D) -> Xt (N,B,D) fp32 + fused bf16 hi/lo split
// =====================================================================
__global__ __launch_bounds__(256) void transpose_kernel(const float* __restrict__ x) {
    int idx = blockIdx.x * 256 + threadIdx.x;
    int d4 = idx & 15;
    int b  = (idx >> 4) & 31;
    int n  = idx >> 9;
    float4 v = *(const float4*)&x[((size_t)b*NN + n)*DD + d4*4];
    size_t off = ((size_t)n*BB + b)*DD + d4*4;
    *(float4*)&g_Xt[off] = v;
    uint2 hi, lo;
    split2(v.x, v.y, hi.x, lo.x);
    split2(v.z, v.w, hi.y, lo.y);
    *(uint2*)&bXh[off] = hi;
    *(uint2*)&bXl[off] = lo;
}

// =====================================================================
// Per-node weight materialization — register-cached pool version.
// Output device symbol resolved in DEVICE code via selector (host
// shadow-symbol ATS hazard — never pass __device__ arrays as host args).
// =====================================================================
__global__ __launch_bounds__(256) void wgen_kernel(int which,
                                                   const float* __restrict__ emb,
                                                   const float* __restrict__ pool) {
    float* out = (which == 0) ? g_Wg : g_Wu;
    __shared__ float es[128*EE];
    const int j4 = blockIdx.x * 256 + threadIdx.x;   // float4 index in [0, PG/4)
    const int nbase = blockIdx.y * 128;
    for (int i = threadIdx.x; i < 128*EE; i += 256)
        es[i] = emb[nbase*EE + i];
    float4 pv[EE];
#pragma unroll
    for (int e = 0; e < EE; e++) pv[e] = ((const float4*)(pool + (size_t)e*PG))[j4];
    __syncthreads();
    for (int n = 0; n < 128; n++) {
        const float* er = es + n*EE;
        float4 a = make_float4(0.f, 0.f, 0.f, 0.f);
#pragma unroll
        for (int e = 0; e < EE; e++) {
            float w = er[e];
            a.x = fmaf(w, pv[e].x, a.x); a.y = fmaf(w, pv[e].y, a.y);
            a.z = fmaf(w, pv[e].z, a.z); a.w = fmaf(w, pv[e].w, a.w);
        }
        ((float4*)(out + (size_t)(nbase + n)*PG))[j4] = a;
    }
}

// =====================================================================
// WMMA bf16-split GEMM: Out = alpha*(A@B) + beta*Cs  [+ fused bf16 split]
// All GEMMs 2048^3. 128x128 tile, 256 threads, 3-stage cp.async, 2 CTAs/SM.
// =====================================================================
__global__ __launch_bounds__(256, 2) void hgemm_kernel(int which) {
    const __nv_bfloat16 *gBh, *gBl;
    float* Out; const float* Cs; float alpha, beta;
    __nv_bfloat16 *Oh, *Ol;
    switch (which) {
        case 0:  gBh = bXh;   gBl = bXl;   Out = g_G1;  Cs = nullptr; alpha = 1.f; beta =  0.f; Oh = bG1h;  Ol = bG1l;  break;
        case 1:  gBh = bG1h;  gBl = bG1l;  Out = g_G2;  Cs = g_Xt;    alpha = 2.f; beta = -1.f; Oh = nullptr; Ol = nullptr; break;
        case 2:  gBh = bCzh;  gBl = bCzl;  Out = g_H1z; Cs = nullptr; alpha = 1.f; beta =  0.f; Oh = bH1zh; Ol = bH1zl; break;
        default: gBh = bH1zh; gBl = bH1zl; Out = g_H2z; Cs = g_Cz;    alpha = 2.f; beta = -1.f; Oh = nullptr; Ol = nullptr; break;
    }
    extern __shared__ __align__(16) char smem[];
    const uint32_t sb = smem_u32(smem);
    const int tid  = threadIdx.x;
    const int lane = tid & 31;
    const int wid  = tid >> 5;
    const int wm   = (wid & 3) * 32;
    const int wn   = (wid >> 2) * 64;
    const int mBase = blockIdx.y * CTM;
    const int nBase = blockIdx.x * CTN;

    const int aRow = tid >> 2,  aC = tid & 3;
    const int bRow = tid >> 4,  bC = tid & 15;
    auto load_stage = [&](int it, int s) {
        const int k0 = it * CTK;
        const uint32_t st = sb + s * STAGE_B;
#pragma unroll
        for (int i = 0; i < 2; i++) {
            int row = aRow + i*64;
            uint32_t d = st + row*(A_LD*2) + aC*16;
            size_t g = (size_t)(mBase + row)*NN + k0 + aC*8;
            CP16(d,            bAh + g);
            CP16(d + A_TILE_B, bAl + g);
        }
#pragma unroll
        for (int i = 0; i < 2; i++) {
            int row = bRow + i*16;
            uint32_t d = st + 2*A_TILE_B + row*(B_LD*2) + bC*16;
            size_t g = (size_t)(k0 + row)*NCOLS + nBase + bC*8;
            CP16(d,            gBh + g);
            CP16(d + B_TILE_B, gBl + g);
        }
        CP_COMMIT();
    };

    wmma::fragment<wmma::accumulator, 16, 16, 16, float> acc[2][4];
#pragma unroll
    for (int mi = 0; mi < 2; mi++)
#pragma unroll
        for (int ni = 0; ni < 4; ni++)
            wmma::fill_fragment(acc[mi][ni], 0.f);

    load_stage(0, 0);
    load_stage(1, 1);

    const int k_iters = NN / CTK;   // 64
    for (int it = 0; it < k_iters; it++) {
        const int s = it % STAGES;
        if (it + 1 < k_iters) { CP_WAIT1(); } else { CP_WAIT0(); }
        __syncthreads();
        if (it + 2 < k_iters) load_stage(it + 2, (it + 2) % STAGES);

        const __nv_bfloat16* Ah = (const __nv_bfloat16*)(smem + s*STAGE_B);
        const __nv_bfloat16* Al = Ah + CTM*A_LD;
        const __nv_bfloat16* Bh = (const __nv_bfloat16*)(smem + s*STAGE_B + 2*A_TILE_B);
        const __nv_bfloat16* Bl = Bh + CTK*B_LD;

#pragma unroll
        for (int kk = 0; kk < CTK; kk += 16) {
            wmma::fragment<wmma::matrix_a, 16, 16, 16, __nv_bfloat16, wmma::row_major> ah[2], al[2];
#pragma unroll
            for (int mi = 0; mi < 2; mi++) {
                wmma::load_matrix_sync(ah[mi], Ah + (wm + mi*16)*A_LD + kk, A_LD);
                wmma::load_matrix_sync(al[mi], Al + (wm + mi*16)*A_LD + kk, A_LD);
            }
#pragma unroll
            for (int ni = 0; ni < 4; ni++) {
                wmma::fragment<wmma::matrix_b, 16, 16, 16, __nv_bfloat16, wmma::row_major> bh, bl;
                wmma::load_matrix_sync(bh, Bh + kk*B_LD + wn + ni*16, B_LD);
                wmma::load_matrix_sync(bl, Bl + kk*B_LD + wn + ni*16, B_LD);
#pragma unroll
                for (int mi = 0; mi < 2; mi++) {
                    wmma::mma_sync(acc[mi][ni], ah[mi], bh, acc[mi][ni]);
                    wmma::mma_sync(acc[mi][ni], al[mi], bh, acc[mi][ni]);
                    wmma::mma_sync(acc[mi][ni], ah[mi], bl, acc[mi][ni]);
                }
            }
        }
        __syncthreads();
    }

    // ---- epilogue via smem staging (documented row-major layout) ----
    __syncthreads();
    float* stage = (float*)smem + wid * (32*64);
#pragma unroll
    for (int mi = 0; mi < 2; mi++)
#pragma unroll
        for (int ni = 0; ni < 4; ni++) {
            if (alpha != 1.f) {
#pragma unroll
                for (int e = 0; e < acc[mi][ni].num_elements; e++)
                    acc[mi][ni].x[e] *= alpha;
            }
            wmma::store_matrix_sync(stage + mi*16*64 + ni*16, acc[mi][ni], 64, wmma::mem_row_major);
        }
    __syncwarp();

    const int col = nBase + wn + lane*2;
    for (int r = 0; r < 32; r++) {
        const int row = mBase + wm + r;
        float2 v = *(const float2*)&stage[r*64 + lane*2];
        const size_t off = (size_t)row*NCOLS + col;
        if (Cs) {
            float2 cv = *(const float2*)&Cs[off];
            v.x = fmaf(beta, cv.x, v.x);
            v.y = fmaf(beta, cv.y, v.y);
        }
        *(float2*)&Out[off] = v;
        if (Oh) {
            uint32_t hi, lo;
            split2(v.x, v.y, hi, lo);
            *(uint32_t*)&Oh[off] = hi;
            *(uint32_t*)&Ol[off] = lo;
        }
    }
}

// =====================================================================
// Gate mix (proven 256-thread scalar): zr = [Xt|G1|G2]_n @ Wg_n + bias
// bias computed in-kernel (bit-identical to old bgen fmaf chain).
// z -> g_Cz (+ fused bf16 split), r -> g_R
// =====================================================================
#define JLDG 193
#define GATE_SMEM ((128 + PG + BB*JLDG) * 4)
__global__ __launch_bounds__(256) void gate_mix_kernel(const float* __restrict__ emb,
                                                       const float* __restrict__ gbp) {
    extern __shared__ float sm[];
    float* Bias = sm;            // 128
    float* Ws   = sm + 128;      // PG
    float* Av   = Ws + PG;       // BB*JLDG
    const int n = blockIdx.x;
    const int tid = threadIdx.x;

    if (tid < D2) {
        float acc = 0.f;
#pragma unroll
        for (int e = 0; e < EE; e++) acc = fmaf(emb[n*EE + e], gbp[e*D2 + tid], acc);
        Bias[tid] = acc;
    }

    const float4* wsrc = (const float4*)(g_Wg + (size_t)n * PG);
    float4* wdst = (float4*)Ws;
    for (int i = tid; i < PG/4; i += 256) wdst[i] = wsrc[i];

    const float* s0 = g_Xt + (size_t)n * (BB*DD);
    const float* s1 = g_G1 + (size_t)n * (BB*DD);
    const float* s2 = g_G2 + (size_t)n * (BB*DD);
    for (int t = tid; t < BB*DD; t += 256) {
        int b = t >> 6, i = t & 63;
        Av[b*JLDG +   0 + i] = s0[t];
        Av[b*JLDG +  64 + i] = s1[t];
        Av[b*JLDG + 128 + i] = s2[t];
    }
    __syncthreads();

    const int tx = tid & 31;
    const int ty = tid >> 5;
    float acc[4][4] = {};
#pragma unroll 4
    for (int j = 0; j < KK*DD; j++) {
        float4 wv = *(const float4*)&Ws[j*D2 + tx*4];
        float a0 = Av[(ty*4 + 0)*JLDG + j];
        float a1 = Av[(ty*4 + 1)*JLDG + j];
        float a2 = Av[(ty*4 + 2)*JLDG + j];
        float a3 = Av[(ty*4 + 3)*JLDG + j];
        acc[0][0] = fmaf(a0, wv.x, acc[0][0]); acc[0][1] = fmaf(a0, wv.y, acc[0][1]);
        acc[0][2] = fmaf(a0, wv.z, acc[0][2]); acc[0][3] = fmaf(a0, wv.w, acc[0][3]);
        acc[1][0] = fmaf(a1, wv.x, acc[1][0]); acc[1][1] = fmaf(a1, wv.y, acc[1][1]);
        acc[1][2] = fmaf(a1, wv.z, acc[1][2]); acc[1][3] = fmaf(a1, wv.w, acc[1][3]);
        acc[2][0] = fmaf(a2, wv.x, acc[2][0]); acc[2][1] = fmaf(a2, wv.y, acc[2][1]);
        acc[2][2] = fmaf(a2, wv.z, acc[2][2]); acc[2][3] = fmaf(a2, wv.w, acc[2][3]);
        acc[3][0] = fmaf(a3, wv.x, acc[3][0]); acc[3][1] = fmaf(a3, wv.y, acc[3][1]);
        acc[3][2] = fmaf(a3, wv.z, acc[3][2]); acc[3][3] = fmaf(a3, wv.w, acc[3][3]);
    }
#pragma unroll
    for (int bb = 0; bb < 4; bb++) {
        const int b = ty*4 + bb;
        float4 sv;
        sv.x = 1.f / (1.f + __expf(-(acc[bb][0] + Bias[tx*4 + 0])));
        sv.y = 1.f / (1.f + __expf(-(acc[bb][1] + Bias[tx*4 + 1])));
        sv.z = 1.f / (1.f + __expf(-(acc[bb][2] + Bias[tx*4 + 2])));
        sv.w = 1.f / (1.f + __expf(-(acc[bb][3] + Bias[tx*4 + 3])));
        if (tx < 16) {   // z half: o = tx*4 .. +3 in [0,64)
            size_t off = ((size_t)n*BB + b)*DD + tx*4;
            *(float4*)&g_Cz[off] = sv;
            uint2 hi, lo;
            split2(sv.x, sv.y, hi.x, lo.x);
            split2(sv.z, sv.w, hi.y, lo.y);
            *(uint2*)&bCzh[off] = hi;
            *(uint2*)&bCzl[off] = lo;
        } else {         // r half
            *(float4*)&g_R[((size_t)n*BB + b)*DD + (tx - 16)*4] = sv;
        }
    }
}

// =====================================================================
// Update mix: hc = tanh([x|z|G1|H1z|G2|H2z]_n (32x384) @ Wu_n (384x64) + bias)
// bias computed in-kernel (bit-identical). h = r*x + (1-r)*hc -> out (B,N,D)
// =====================================================================
#define JLDU 385
#define UPD_SMEM ((64 + PU + BB*JLDU) * 4)
__global__ __launch_bounds__(256) void update_mix_kernel(const float* __restrict__ emb,
                                                         const float* __restrict__ ubp,
                                                         float* __restrict__ out) {
    extern __shared__ float sm[];
    float* Bias = sm;            // 64
    float* Ws   = sm + 64;       // PU
    float* Av   = Ws + PU;       // BB*JLDU
    const int n = blockIdx.x;
    const int tid = threadIdx.x;

    if (tid < DD) {
        float acc = 0.f;
#pragma unroll
        for (int e = 0; e < EE; e++) acc = fmaf(emb[n*EE + e], ubp[e*DD + tid], acc);
        Bias[tid] = acc;
    }

    const float4* wsrc = (const float4*)(g_Wu + (size_t)n * PU);
    float4* wdst = (float4*)Ws;
    for (int i = tid; i < PU/4; i += 256) wdst[i] = wsrc[i];

    const size_t base = (size_t)n * (BB*DD);
    const float* s0 = g_Xt  + base;
    const float* s1 = g_Cz  + base;
    const float* s2 = g_G1  + base;
    const float* s3 = g_H1z + base;
    const float* s4 = g_G2  + base;
    const float* s5 = g_H2z + base;
    for (int t = tid; t < BB*DD; t += 256) {
        int b = t >> 6, i = t & 63;
        float* av = Av + b*JLDU + i;
        av[  0] = s0[t];
        av[ 64] = s1[t];
        av[128] = s2[t];
        av[192] = s3[t];
        av[256] = s4[t];
        av[320] = s5[t];
    }
    __syncthreads();

    const int tx = tid & 15;
    const int ty = tid >> 4;
    float acc[2][4] = {};
#pragma unroll 4
    for (int j = 0; j < KK*D2; j++) {
        float4 wv = *(const float4*)&Ws[j*DD + tx*4];
        float a0 = Av[(ty*2 + 0)*JLDU + j];
        float a1 = Av[(ty*2 + 1)*JLDU + j];
        acc[0][0] = fmaf(a0, wv.x, acc[0][0]); acc[0][1] = fmaf(a0, wv.y, acc[0][1]);
        acc[0][2] = fmaf(a0, wv.z, acc[0][2]); acc[0][3] = fmaf(a0, wv.w, acc[0][3]);
        acc[1][0] = fmaf(a1, wv.x, acc[1][0]); acc[1][1] = fmaf(a1, wv.y, acc[1][1]);
        acc[1][2] = fmaf(a1, wv.z, acc[1][2]); acc[1][3] = fmaf(a1, wv.w, acc[1][3]);
    }
#pragma unroll
    for (int bb = 0; bb < 2; bb++) {
        int b = ty*2 + bb;
#pragma unroll
        for (int oo = 0; oo < 4; oo++) {
            int o = tx*4 + oo;
            float v  = acc[bb][oo] + Bias[o];
            float hc = tanhf(v);
            float r  = g_R [((size_t)n*BB + b)*DD + o];
            float xv = g_Xt[((size_t)n*BB + b)*DD + o];
            out[(size_t)b*(NN*DD) + (size_t)n*DD + o] = fmaf(r, xv - hc, hc);
        }
    }
}

// =====================================================================
// Launch
// =====================================================================
extern "C" void kernel_launch(void* const* d_in, const int* in_sizes, int n_in,
                              void* d_out, int out_size) {
    const float* x   = (const float*)d_in[0];
    const float* emb = (const float*)d_in[2];
    const float* gwp = (const float*)d_in[3];
    const float* gbp = (const float*)d_in[4];
    const float* uwp = (const float*)d_in[5];
    const float* ubp = (const float*)d_in[6];
    float* out = (float*)d_out;

    cudaFuncSetAttribute(gate_mix_kernel,   cudaFuncAttributeMaxDynamicSharedMemorySize, GATE_SMEM);
    cudaFuncSetAttribute(update_mix_kernel, cudaFuncAttributeMaxDynamicSharedMemorySize, UPD_SMEM);
    cudaFuncSetAttribute(hgemm_kernel,      cudaFuncAttributeMaxDynamicSharedMemorySize, HG_SMEM);

    const dim3 GEMM_GRID(NCOLS/CTN, NN/CTM);   // (16, 16) = 256 CTAs — 1 wave @ occ 2

    adj_kernel<<<NN, 256>>>(emb);                            // adj -> bAh/bAl (fused)
    transpose_kernel<<<(NN*BB*16)/256, 256>>>(x);            // Xt + bXh/bXl (fused)
    wgen_kernel<<<dim3(PG/1024, NN/128), 256>>>(0, emb, gwp);
    wgen_kernel<<<dim3(PU/1024, NN/128), 256>>>(1, emb, uwp);

    hgemm_kernel<<<GEMM_GRID, 256, HG_SMEM>>>(0);            // G1 = A@x (+split)
    hgemm_kernel<<<GEMM_GRID, 256, HG_SMEM>>>(1);            // G2 = 2A@G1 - x

    gate_mix_kernel<<<NN, 256, GATE_SMEM>>>(emb, gbp);       // z (+split), r, bias fused

    hgemm_kernel<<<GEMM_GRID, 256, HG_SMEM>>>(2);            // H1z = A@z (+split)
    hgemm_kernel<<<GEMM_GRID, 256, HG_SMEM>>>(3);            // H2z = 2A@H1z - z

    update_mix_kernel<<<NN, 256, UPD_SMEM>>>(emb, ubp, out); // bias fused
}